// round 3
// baseline (speedup 1.0000x reference)
#include <cuda_runtime.h>

// Problem constants
#define B_   16
#define C_   32
#define NK_  32
#define H_   384
#define W_   384
#define HW_  (H_ * W_)
#define HID_ 128
#define KK_  9            // 3x3
#define NKERN_ (NK_ * KK_) // 288 per batch

// Scratch (allocation-free rule: device globals)
__device__ float g_pooled[B_ * C_];        // 512
__device__ float g_kern[B_ * NKERN_];      // 4608

// ---------------------------------------------------------------------------
// Kernel 1: global average pool per (b, c) plane. grid = B*C, block = 512.
// ---------------------------------------------------------------------------
__global__ void pool_kernel(const float* __restrict__ x) {
    const int bc = blockIdx.x;
    const float4* p = reinterpret_cast<const float4*>(x + (size_t)bc * HW_);
    float s = 0.0f;
    const int n4 = HW_ / 4; // 36864
    for (int i = threadIdx.x; i < n4; i += blockDim.x) {
        float4 v = p[i];
        s += (v.x + v.y) + (v.z + v.w);
    }
    // warp reduce
    #pragma unroll
    for (int o = 16; o > 0; o >>= 1) s += __shfl_xor_sync(0xFFFFFFFFu, s, o);
    __shared__ float ws[16];
    const int lane = threadIdx.x & 31, wid = threadIdx.x >> 5;
    if (lane == 0) ws[wid] = s;
    __syncthreads();
    if (wid == 0) {
        s = (lane < (blockDim.x >> 5)) ? ws[lane] : 0.0f;
        #pragma unroll
        for (int o = 8; o > 0; o >>= 1) s += __shfl_xor_sync(0xFFFFFFFFu, s, o);
        if (lane == 0) g_pooled[bc] = s * (1.0f / (float)HW_);
    }
}

// ---------------------------------------------------------------------------
// Kernel 2: per-sample MLP -> 3x3 kernels. grid = B, block = 288.
//   hdn = relu(pooled @ w1 + b1)   [128]
//   kern = hdn @ w2 + b2           [288]
// ---------------------------------------------------------------------------
__global__ void mlp_kernel(const float* __restrict__ w1, const float* __restrict__ b1,
                           const float* __restrict__ w2, const float* __restrict__ b2) {
    const int b = blockIdx.x;
    __shared__ float sp[C_];
    __shared__ float sh[HID_];
    const int t = threadIdx.x;
    if (t < C_) sp[t] = g_pooled[b * C_ + t];
    __syncthreads();
    if (t < HID_) {
        float a = b1[t];
        #pragma unroll
        for (int c = 0; c < C_; c++) a = fmaf(sp[c], w1[c * HID_ + t], a);
        sh[t] = fmaxf(a, 0.0f);
    }
    __syncthreads();
    // t in [0, 288)
    float a = b2[t];
    #pragma unroll 8
    for (int j = 0; j < HID_; j++) a = fmaf(sh[j], w2[j * NKERN_ + t], a);
    g_kern[b * NKERN_ + t] = a;
}

// ---------------------------------------------------------------------------
// Kernel 3: depthwise 3x3 conv, per-sample dynamic weights, zero padding.
// Tile: full width (384) x 16 rows, +2 halo rows in smem.
// smem row stride 392 floats: 392 % 4 == 0 so float4 reads at col = 4*tx are
// aligned & conflict-free; 392 % 32 == 8 staggers rows across banks.
// blockDim = (96, 8): each thread emits 2 float4 rows (ty, ty+8).
// grid = (H/16, NK, B) = (24, 32, 16)
// ---------------------------------------------------------------------------
#define TILE_H 16
#define SM_STRIDE 392  // 1 left pad + 384 data + 1 right pad + 6 align pad

__global__ __launch_bounds__(768)
void conv_kernel(const float* __restrict__ x, float* __restrict__ out) {
    const int tileY = blockIdx.x;
    const int bk    = blockIdx.z * NK_ + blockIdx.y;
    const float* img = x   + (size_t)bk * HW_;
    float*       dst = out + (size_t)bk * HW_;

    __shared__ float sm[(TILE_H + 2) * SM_STRIDE];

    const int tid  = threadIdx.y * 96 + threadIdx.x; // 0..767
    const int base = tileY * TILE_H;

    // zero the left/right pad columns
    if (tid < (TILE_H + 2)) {
        sm[tid * SM_STRIDE + 0]      = 0.0f;
        sm[tid * SM_STRIDE + W_ + 1] = 0.0f;
    }

    // load rows base-1 .. base+TILE_H into sm[r][1..384]
    const int n4 = (TILE_H + 2) * (W_ / 4); // 1728
    for (int idx = tid; idx < n4; idx += 768) {
        const int r  = idx / (W_ / 4);
        const int c4 = idx % (W_ / 4);
        const int gy = base - 1 + r;
        float4 v;
        if (gy >= 0 && gy < H_) v = *reinterpret_cast<const float4*>(img + (size_t)gy * W_ + c4 * 4);
        else                    v = make_float4(0.f, 0.f, 0.f, 0.f);
        float* d = &sm[r * SM_STRIDE + c4 * 4 + 1];
        d[0] = v.x; d[1] = v.y; d[2] = v.z; d[3] = v.w;
    }
    __syncthreads();

    // broadcast the 9 dynamic weights
    float w[9];
    const float* kp = g_kern + bk * KK_;
    #pragma unroll
    for (int i = 0; i < 9; i++) w[i] = __ldg(kp + i);

    const int c0 = threadIdx.x * 4; // output col base; smem idx c0..c0+5 needed

    #pragma unroll
    for (int rr = 0; rr < 2; rr++) {
        const int ty = threadIdx.y + rr * 8;       // output row offset in tile
        float a0 = 0.f, a1 = 0.f, a2 = 0.f, a3 = 0.f;
        #pragma unroll
        for (int dy = 0; dy < 3; dy++) {
            const float* row = &sm[(ty + dy) * SM_STRIDE + c0];
            // aligned float4 loads: cols c0..c0+3 and c0+4..c0+7 (use 6)
            float4 lo = *reinterpret_cast<const float4*>(row);
            float4 hi = *reinterpret_cast<const float4*>(row + 4);
            const float w0 = w[dy * 3 + 0], w1v = w[dy * 3 + 1], w2v = w[dy * 3 + 2];
            a0 = fmaf(w0, lo.x, a0); a0 = fmaf(w1v, lo.y, a0); a0 = fmaf(w2v, lo.z, a0);
            a1 = fmaf(w0, lo.y, a1); a1 = fmaf(w1v, lo.z, a1); a1 = fmaf(w2v, lo.w, a1);
            a2 = fmaf(w0, lo.z, a2); a2 = fmaf(w1v, lo.w, a2); a2 = fmaf(w2v, hi.x, a2);
            a3 = fmaf(w0, lo.w, a3); a3 = fmaf(w1v, hi.x, a3); a3 = fmaf(w2v, hi.y, a3);
        }
        const int orow = base + ty;
        *reinterpret_cast<float4*>(dst + (size_t)orow * W_ + c0) = make_float4(a0, a1, a2, a3);
    }
}

// ---------------------------------------------------------------------------
extern "C" void kernel_launch(void* const* d_in, const int* in_sizes, int n_in,
                              void* d_out, int out_size) {
    const float* x  = (const float*)d_in[0];
    const float* w1 = (const float*)d_in[1];
    const float* b1 = (const float*)d_in[2];
    const float* w2 = (const float*)d_in[3];
    const float* b2 = (const float*)d_in[4];
    float* out = (float*)d_out;

    pool_kernel<<<B_ * C_, 512>>>(x);
    mlp_kernel<<<B_, NKERN_>>>(w1, b1, w2, b2);
    dim3 grid(H_ / TILE_H, NK_, B_);
    dim3 block(96, 8);
    conv_kernel<<<grid, block>>>(x, out);
}

// round 4
// speedup vs baseline: 1.0004x; 1.0004x over previous
#include <cuda_runtime.h>

// Problem constants
#define B_   16
#define C_   32
#define NK_  32
#define H_   384
#define W_   384
#define HW_  (H_ * W_)
#define HID_ 128
#define KK_  9            // 3x3
#define NKERN_ (NK_ * KK_) // 288 per batch

// Scratch (allocation-free rule: device globals)
__device__ float g_pooled[B_ * C_];        // 512
__device__ float g_kern[B_ * NKERN_];      // 4608

// ---------------------------------------------------------------------------
// Kernel 1: global average pool per (b, c) plane. grid = B*C, block = 512.
// ---------------------------------------------------------------------------
__global__ void pool_kernel(const float* __restrict__ x) {
    const int bc = blockIdx.x;
    const float4* p = reinterpret_cast<const float4*>(x + (size_t)bc * HW_);
    float s = 0.0f;
    const int n4 = HW_ / 4; // 36864
    for (int i = threadIdx.x; i < n4; i += blockDim.x) {
        float4 v = p[i];
        s += (v.x + v.y) + (v.z + v.w);
    }
    // warp reduce
    #pragma unroll
    for (int o = 16; o > 0; o >>= 1) s += __shfl_xor_sync(0xFFFFFFFFu, s, o);
    __shared__ float ws[16];
    const int lane = threadIdx.x & 31, wid = threadIdx.x >> 5;
    if (lane == 0) ws[wid] = s;
    __syncthreads();
    if (wid == 0) {
        s = (lane < (blockDim.x >> 5)) ? ws[lane] : 0.0f;
        #pragma unroll
        for (int o = 8; o > 0; o >>= 1) s += __shfl_xor_sync(0xFFFFFFFFu, s, o);
        if (lane == 0) g_pooled[bc] = s * (1.0f / (float)HW_);
    }
}

// ---------------------------------------------------------------------------
// Kernel 2: per-sample MLP -> 3x3 kernels. grid = B, block = 288.
//   hdn = relu(pooled @ w1 + b1)   [128]
//   kern = hdn @ w2 + b2           [288]
// ---------------------------------------------------------------------------
__global__ void mlp_kernel(const float* __restrict__ w1, const float* __restrict__ b1,
                           const float* __restrict__ w2, const float* __restrict__ b2) {
    const int b = blockIdx.x;
    __shared__ float sp[C_];
    __shared__ float sh[HID_];
    const int t = threadIdx.x;
    if (t < C_) sp[t] = g_pooled[b * C_ + t];
    __syncthreads();
    if (t < HID_) {
        float a = b1[t];
        #pragma unroll
        for (int c = 0; c < C_; c++) a = fmaf(sp[c], w1[c * HID_ + t], a);
        sh[t] = fmaxf(a, 0.0f);
    }
    __syncthreads();
    // t in [0, 288)
    float a = b2[t];
    #pragma unroll 8
    for (int j = 0; j < HID_; j++) a = fmaf(sh[j], w2[j * NKERN_ + t], a);
    g_kern[b * NKERN_ + t] = a;
}

// ---------------------------------------------------------------------------
// Kernel 3: depthwise 3x3 conv, per-sample dynamic weights, zero padding.
// Tile: full width (384) x 16 rows, +2 halo rows in smem.
// smem row stride 392 floats: 392 % 4 == 0 so float4 reads at col = 4*tx are
// aligned & conflict-free; 392 % 32 == 8 staggers rows across banks.
// blockDim = (96, 8): each thread emits 2 float4 rows (ty, ty+8).
// grid = (H/16, NK, B) = (24, 32, 16)
// ---------------------------------------------------------------------------
#define TILE_H 16
#define SM_STRIDE 392  // 1 left pad + 384 data + 1 right pad + 6 align pad

__global__ __launch_bounds__(768)
void conv_kernel(const float* __restrict__ x, float* __restrict__ out) {
    const int tileY = blockIdx.x;
    const int bk    = blockIdx.z * NK_ + blockIdx.y;
    const float* img = x   + (size_t)bk * HW_;
    float*       dst = out + (size_t)bk * HW_;

    __shared__ float sm[(TILE_H + 2) * SM_STRIDE];

    const int tid  = threadIdx.y * 96 + threadIdx.x; // 0..767
    const int base = tileY * TILE_H;

    // zero the left/right pad columns
    if (tid < (TILE_H + 2)) {
        sm[tid * SM_STRIDE + 0]      = 0.0f;
        sm[tid * SM_STRIDE + W_ + 1] = 0.0f;
    }

    // load rows base-1 .. base+TILE_H into sm[r][1..384]
    const int n4 = (TILE_H + 2) * (W_ / 4); // 1728
    for (int idx = tid; idx < n4; idx += 768) {
        const int r  = idx / (W_ / 4);
        const int c4 = idx % (W_ / 4);
        const int gy = base - 1 + r;
        float4 v;
        if (gy >= 0 && gy < H_) v = *reinterpret_cast<const float4*>(img + (size_t)gy * W_ + c4 * 4);
        else                    v = make_float4(0.f, 0.f, 0.f, 0.f);
        float* d = &sm[r * SM_STRIDE + c4 * 4 + 1];
        d[0] = v.x; d[1] = v.y; d[2] = v.z; d[3] = v.w;
    }
    __syncthreads();

    // broadcast the 9 dynamic weights
    float w[9];
    const float* kp = g_kern + bk * KK_;
    #pragma unroll
    for (int i = 0; i < 9; i++) w[i] = __ldg(kp + i);

    const int c0 = threadIdx.x * 4; // output col base; smem idx c0..c0+5 needed

    #pragma unroll
    for (int rr = 0; rr < 2; rr++) {
        const int ty = threadIdx.y + rr * 8;       // output row offset in tile
        float a0 = 0.f, a1 = 0.f, a2 = 0.f, a3 = 0.f;
        #pragma unroll
        for (int dy = 0; dy < 3; dy++) {
            const float* row = &sm[(ty + dy) * SM_STRIDE + c0];
            // aligned float4 loads: cols c0..c0+3 and c0+4..c0+7 (use 6)
            float4 lo = *reinterpret_cast<const float4*>(row);
            float4 hi = *reinterpret_cast<const float4*>(row + 4);
            const float w0 = w[dy * 3 + 0], w1v = w[dy * 3 + 1], w2v = w[dy * 3 + 2];
            a0 = fmaf(w0, lo.x, a0); a0 = fmaf(w1v, lo.y, a0); a0 = fmaf(w2v, lo.z, a0);
            a1 = fmaf(w0, lo.y, a1); a1 = fmaf(w1v, lo.z, a1); a1 = fmaf(w2v, lo.w, a1);
            a2 = fmaf(w0, lo.z, a2); a2 = fmaf(w1v, lo.w, a2); a2 = fmaf(w2v, hi.x, a2);
            a3 = fmaf(w0, lo.w, a3); a3 = fmaf(w1v, hi.x, a3); a3 = fmaf(w2v, hi.y, a3);
        }
        const int orow = base + ty;
        *reinterpret_cast<float4*>(dst + (size_t)orow * W_ + c0) = make_float4(a0, a1, a2, a3);
    }
}

// ---------------------------------------------------------------------------
extern "C" void kernel_launch(void* const* d_in, const int* in_sizes, int n_in,
                              void* d_out, int out_size) {
    const float* x  = (const float*)d_in[0];
    const float* w1 = (const float*)d_in[1];
    const float* b1 = (const float*)d_in[2];
    const float* w2 = (const float*)d_in[3];
    const float* b2 = (const float*)d_in[4];
    float* out = (float*)d_out;

    pool_kernel<<<B_ * C_, 512>>>(x);
    mlp_kernel<<<B_, NKERN_>>>(w1, b1, w2, b2);
    dim3 grid(H_ / TILE_H, NK_, B_);
    dim3 block(96, 8);
    conv_kernel<<<grid, block>>>(x, out);
}